// round 15
// baseline (speedup 1.0000x reference)
#include <cuda_runtime.h>
#include <cuda_bf16.h>
#include <math.h>
#include <math_constants.h>
#include <cstdint>

#define NPTS 8192
#define DIM  128
#define KNB  8
#define NB   64            // 8192/128 blocks per side
#define SLOTS 128          // per row: exactly 64 used (64-br row-side + br col-side)
#define COLBASE 64

// ------------------------- device scratch (no allocs) -----------------------
__device__ float g_sq[NPTS];
__device__ float g_loss[NPTS];
__device__ float g_pden[(size_t)NPTS * SLOTS];
__device__ float g_cand[(size_t)NPTS * SLOTS * KNB];
__device__ uint4 g_ph[(size_t)NPTS * 16];   // 128 bf16 (hi) per row

// ------------------------- helpers ------------------------------------------
__device__ __forceinline__ uint32_t smem_u32(const void* p) {
    uint32_t a;
    asm("{ .reg .u64 t; cvta.to.shared.u64 t, %1; cvt.u32.u64 %0, t; }"
        : "=r"(a) : "l"(p));
    return a;
}
#define SWZ(o) ((o) ^ (((o) >> 3) & 0x70))

#define CP_ASYNC16(dst, src) \
    asm volatile("cp.async.cg.shared.global [%0], [%1], 16;" \
                 :: "r"(dst), "l"(src) : "memory")
#define CP_COMMIT() asm volatile("cp.async.commit_group;" ::: "memory")
#define CP_WAIT(N)  asm volatile("cp.async.wait_group %0;" :: "n"(N) : "memory")

#define LDSM_X4(r0, r1, r2, r3, a) \
    asm volatile("ldmatrix.sync.aligned.m8n8.x4.shared.b16 {%0,%1,%2,%3}, [%4];" \
                 : "=r"(r0), "=r"(r1), "=r"(r2), "=r"(r3) : "r"(a))

#define MMA_BF16(c, a, b) \
    asm volatile("mma.sync.aligned.m16n8k16.row.col.f32.bf16.bf16.f32 " \
                 "{%0,%1,%2,%3}, {%4,%5,%6,%7}, {%8,%9}, {%0,%1,%2,%3};" \
                 : "+f"((c)[0]), "+f"((c)[1]), "+f"((c)[2]), "+f"((c)[3]) \
                 : "r"((a)[0]), "r"((a)[1]), "r"((a)[2]), "r"((a)[3]), \
                   "r"((b)[0]), "r"((b)[1]))

// SMEM: A tile 32KB at 0, B tile 32KB at 32KB (aliased to A on diagonal).
// After mainloop the tile area is reused for candidate staging (28KB).
// 2 CTAs/SM -> 128KB of 227KB.
#define OFF_B    32768
#define SMEM_TOTAL 65536

// ---- MUFU transcendentals ---------------------------------------------------
__device__ __forceinline__ float rsqrt_ap(float x) {
    float y; asm("rsqrt.approx.f32 %0, %1;" : "=f"(y) : "f"(x)); return y;
}
__device__ __forceinline__ float ex2_ap(float x) {
    float y; asm("ex2.approx.f32 %0, %1;" : "=f"(y) : "f"(x)); return y;
}

// ---- sorting networks -------------------------------------------------------
__device__ __forceinline__ void cas(float& a, float& b) {
    float lo = fminf(a, b), hi = fmaxf(a, b); a = lo; b = hi;
}
__device__ __forceinline__ void sort8(float* v) {
    cas(v[0],v[1]); cas(v[2],v[3]); cas(v[4],v[5]); cas(v[6],v[7]);
    cas(v[0],v[2]); cas(v[1],v[3]); cas(v[4],v[6]); cas(v[5],v[7]);
    cas(v[1],v[2]); cas(v[5],v[6]);
    cas(v[0],v[4]); cas(v[1],v[5]); cas(v[2],v[6]); cas(v[3],v[7]);
    cas(v[2],v[4]); cas(v[3],v[5]);
    cas(v[1],v[2]); cas(v[3],v[4]); cas(v[5],v[6]);
}
__device__ __forceinline__ void bitonic8(float* v) {
    cas(v[0],v[4]); cas(v[1],v[5]); cas(v[2],v[6]); cas(v[3],v[7]);
    cas(v[0],v[2]); cas(v[1],v[3]); cas(v[4],v[6]); cas(v[5],v[7]);
    cas(v[0],v[1]); cas(v[2],v[3]); cas(v[4],v[5]); cas(v[6],v[7]);
}
__device__ __forceinline__ void merge8(float* t, const float* o) {
    float m[8];
    #pragma unroll
    for (int q = 0; q < 8; q++) m[q] = fminf(t[q], o[7 - q]);
    bitonic8(m);
    #pragma unroll
    for (int q = 0; q < 8; q++) t[q] = m[q];
}
__device__ __forceinline__ void merge8_shfl(float* t, int mask) {
    float o[8];
    #pragma unroll
    for (int q = 0; q < 8; q++) o[q] = __shfl_xor_sync(0xffffffffu, t[7 - q], mask);
    #pragma unroll
    for (int q = 0; q < 8; q++) t[q] = fminf(t[q], o[q]);
    bitonic8(t);
}
// level-1 work-split merge: lane owns one of the two lists (ownb selects),
// exchanges the non-owned one with the xor-mask partner.
__device__ __forceinline__ void merge8_pair(float* r, const float* va,
                                            const float* vb, bool ownb,
                                            int mask) {
    #pragma unroll
    for (int q = 0; q < 8; q++) {
        float sendv = ownb ? va[7 - q] : vb[7 - q];
        float recvv = __shfl_xor_sync(0xffffffffu, sendv, mask);
        float minev = ownb ? vb[q] : va[q];
        r[q] = fminf(minev, recvv);
    }
    bitonic8(r);
}

// ---------------------------------------------------------------------------
// fused pack (hi only) + sqnorm: one warp per row
// ---------------------------------------------------------------------------
__global__ void pack_kernel(const float* __restrict__ x, int n) {
    int warp = (blockIdx.x * blockDim.x + threadIdx.x) >> 5;
    int lane = threadIdx.x & 31;
    if (warp >= n) return;
    float4 v = ((const float4*)(x + (size_t)warp * DIM))[lane];

    float s = v.x * v.x + v.y * v.y + v.z * v.z + v.w * v.w;
    #pragma unroll
    for (int o = 16; o; o >>= 1) s += __shfl_xor_sync(0xffffffffu, s, o);
    if (lane == 0) g_sq[warp] = s;

    __nv_bfloat162* ph2 = (__nv_bfloat162*)g_ph;   // 64 pairs per row
    size_t rb = (size_t)warp * 64;
    ph2[rb + lane * 2]     = __nv_bfloat162(__float2bfloat16(v.x), __float2bfloat16(v.y));
    ph2[rb + lane * 2 + 1] = __nv_bfloat162(__float2bfloat16(v.z), __float2bfloat16(v.w));
}

// ---------------------------------------------------------------------------
// Symmetric fused GEMM: 128x128 tiles over upper triangle, warps 2(m)x4(n)
// of 64x32. K=128 hi-only bf16. In-CTA candidate consolidation:
// 1 row slot + 1 col slot per point per tile. 2 CTAs/SM.
// ---------------------------------------------------------------------------
__global__ __launch_bounds__(256, 2) void fused_gemm(int n) {
    extern __shared__ __align__(16) char smem[];
    const uint32_t sb = smem_u32(smem);
    const int tid = threadIdx.x;
    const int wid = tid >> 5;
    const int lane = tid & 31;
    const int wm = wid & 1;          // 64-row half
    const int wn = wid >> 1;         // 32-col strip
    const int mr = wm * 64;
    const int nr = wn * 32;

    int rem = blockIdx.x, bi = 0;
    while (rem >= NB - bi) { rem -= NB - bi; bi++; }
    const int bj = bi + rem;
    const int i0 = bi * 128, j0 = bj * 128;
    const bool diag = (bi == bj);

    // prologue: A tile; B tile unless diagonal (B aliases A).
    #pragma unroll
    for (int r = 0; r < 8; r++) {
        int idx = tid + r * 256;                  // 0..2047
        int kc = idx >> 10, w = idx & 1023;
        int row = w >> 3, q = w & 7;
        const uint4* src = &g_ph[(size_t)(i0 + row) * 16 + kc * 8 + q];
        CP_ASYNC16(sb + kc * 16384 + SWZ(row * 128 + q * 16), src);
    }
    if (!diag) {
        #pragma unroll
        for (int r = 0; r < 8; r++) {
            int idx = tid + r * 256;
            int kc = idx >> 10, w = idx & 1023;
            int row = w >> 3, q = w & 7;
            const uint4* src = &g_ph[(size_t)(j0 + row) * 16 + kc * 8 + q];
            CP_ASYNC16(sb + OFF_B + kc * 16384 + SWZ(row * 128 + q * 16), src);
        }
    }
    CP_COMMIT();
    CP_WAIT(0);
    __syncthreads();

    const uint32_t bbase = diag ? sb : (sb + OFF_B);
    const int row_off = lane & 15;
    const int colh2 = (lane >> 4) * 16;
    const uint32_t aRow = (uint32_t)(mr + row_off) * 128;
    const uint32_t bRow = (uint32_t)(nr + row_off) * 128;

    float acc[4][4][4];
    #pragma unroll
    for (int i = 0; i < 4; i++)
        #pragma unroll
        for (int j = 0; j < 4; j++)
            #pragma unroll
            for (int q = 0; q < 4; q++) acc[i][j][q] = 0.0f;

    #pragma unroll
    for (int c = 0; c < 2; c++) {
        uint32_t sA = sb + c * 16384;
        uint32_t sB = bbase + c * 16384;
        #pragma unroll
        for (int ks = 0; ks < 4; ks++) {
            uint32_t colb = ks * 32 + colh2;
            uint32_t aF[4][4], bF[4][2];
            #pragma unroll
            for (int i = 0; i < 4; i++) {
                uint32_t ad = sA + SWZ(aRow + i * 2048 + colb);
                LDSM_X4(aF[i][0], aF[i][1], aF[i][2], aF[i][3], ad);
            }
            #pragma unroll
            for (int jj = 0; jj < 2; jj++) {
                uint32_t r0, r1, r2, r3;
                uint32_t bd = sB + SWZ(bRow + jj * 2048 + colb);
                LDSM_X4(r0, r1, r2, r3, bd);
                bF[2 * jj][0] = r0; bF[2 * jj][1] = r2;
                bF[2 * jj + 1][0] = r1; bF[2 * jj + 1][1] = r3;
            }
            #pragma unroll
            for (int i = 0; i < 4; i++)
                #pragma unroll
                for (int j = 0; j < 4; j++)
                    MMA_BF16(acc[i][j], aF[i], bF[j]);
        }
    }

    // tiles no longer needed; SMEM becomes candidate staging after this sync
    __syncthreads();
    float4* rowc4   = (float4*)smem;             // [128 rows][4 strips][2] = 16KB
    float*  rowden_s = (float*)(smem + 16384);   // [128][4] = 2KB
    float4* colc4   = (float4*)(smem + 18432);   // [128 cols][2 halves][2] = 8KB
    float*  colden_s = (float*)(smem + 26624);   // [128][2] = 1KB

    // ---------------- phase A: per-warp stats into SMEM ----------------
    const int g = lane >> 2, t = lane & 3;
    const int scol = j0 + nr + t * 2;
    const float NL2E = -1.4426950408889634f;

    float sqc[8], sqr[8], colden[8];
    #pragma unroll
    for (int j = 0; j < 4; j++) {
        #pragma unroll
        for (int e = 0; e < 2; e++) {
            sqc[j * 2 + e] = g_sq[scol + j * 8 + e];
            colden[j * 2 + e] = 0.0f;
        }
    }
    #pragma unroll
    for (int i = 0; i < 4; i++)
        #pragma unroll
        for (int h = 0; h < 2; h++)
            sqr[i * 2 + h] = g_sq[i0 + mr + i * 16 + h * 8 + g];

    const bool own_h1 = (lane & 1);          // t parity: odd t owns h=1
    #pragma unroll
    for (int i = 0; i < 4; i++) {
        const int rga = i0 + mr + i * 16 + g;       // h = 0
        const int rgb = rga + 8;                    // h = 1
        const float sqia = sqr[i * 2], sqib = sqr[i * 2 + 1];
        float v8a[8], v8b[8];
        float den_a = 0.0f, den_b = 0.0f;
        #pragma unroll
        for (int j = 0; j < 4; j++) {
            #pragma unroll
            for (int e = 0; e < 2; e++) {
                const int je = j * 2 + e;
                const int cg = scol + j * 8 + e;
                float d2a = fmaxf(fmaf(-2.0f, acc[i][j][e], sqia + sqc[je]), 0.0f);
                bool sa = diag && (cg == rga);
                float exa = ex2_ap(d2a * rsqrt_ap(d2a) * NL2E);
                exa = sa ? 0.0f : exa;
                den_a += exa; colden[je] += exa;
                v8a[je] = sa ? CUDART_INF_F : d2a;

                float d2b = fmaxf(fmaf(-2.0f, acc[i][j][2 + e], sqib + sqc[je]), 0.0f);
                bool sbx = diag && (cg == rgb);
                float exb = ex2_ap(d2b * rsqrt_ap(d2b) * NL2E);
                exb = sbx ? 0.0f : exb;
                den_b += exb; colden[je] += exb;
                v8b[je] = sbx ? CUDART_INF_F : d2b;
            }
        }
        den_a += __shfl_xor_sync(0xffffffffu, den_a, 1);
        den_a += __shfl_xor_sync(0xffffffffu, den_a, 2);
        den_b += __shfl_xor_sync(0xffffffffu, den_b, 1);
        den_b += __shfl_xor_sync(0xffffffffu, den_b, 2);
        sort8(v8a); sort8(v8b);
        float r8[8];
        merge8_pair(r8, v8a, v8b, own_h1, 1);   // t0<->t1, t2<->t3
        merge8_shfl(r8, 2);                     // complete over 4 t-lanes
        if (t < 2) {                            // t==0 owns h=0, t==1 h=1
            const int lr = mr + i * 16 + (own_h1 ? 8 : 0) + g;
            float4* d = &rowc4[(lr * 4 + wn) * 2];
            d[0] = make_float4(r8[0], r8[1], r8[2], r8[3]);
            d[1] = make_float4(r8[4], r8[5], r8[6], r8[7]);
            rowden_s[lr * 4 + wn] = own_h1 ? den_b : den_a;
        }
    }

    if (!diag) {
        const bool own_e1 = (lane >> 2) & 1;    // g parity: odd g owns e=1
        #pragma unroll
        for (int j = 0; j < 4; j++) {
            float c8a[8], c8b[8];
            #pragma unroll
            for (int i = 0; i < 4; i++) {
                #pragma unroll
                for (int h = 0; h < 2; h++) {
                    float sq_ih = sqr[i * 2 + h];
                    c8a[i * 2 + h] = fmaxf(fmaf(-2.0f, acc[i][j][h * 2],     sq_ih + sqc[j * 2]),     0.0f);
                    c8b[i * 2 + h] = fmaxf(fmaf(-2.0f, acc[i][j][h * 2 + 1], sq_ih + sqc[j * 2 + 1]), 0.0f);
                }
            }
            sort8(c8a); sort8(c8b);
            float r8[8];
            merge8_pair(r8, c8a, c8b, own_e1, 4);   // g pairs
            merge8_shfl(r8, 8);
            merge8_shfl(r8, 16);                    // complete over 8 g-lanes
            float cda = colden[j * 2], cdb = colden[j * 2 + 1];
            cda += __shfl_xor_sync(0xffffffffu, cda, 4);
            cda += __shfl_xor_sync(0xffffffffu, cda, 8);
            cda += __shfl_xor_sync(0xffffffffu, cda, 16);
            cdb += __shfl_xor_sync(0xffffffffu, cdb, 4);
            cdb += __shfl_xor_sync(0xffffffffu, cdb, 8);
            cdb += __shfl_xor_sync(0xffffffffu, cdb, 16);
            if (g < 2) {                            // g==0 owns e=0, g==1 e=1
                const int lc = nr + j * 8 + t * 2 + (own_e1 ? 1 : 0);
                float4* d = &colc4[(lc * 2 + wm) * 2];
                d[0] = make_float4(r8[0], r8[1], r8[2], r8[3]);
                d[1] = make_float4(r8[4], r8[5], r8[6], r8[7]);
                colden_s[lc * 2 + wm] = own_e1 ? cdb : cda;
            }
        }
    }
    __syncthreads();

    // ---------------- phase B: consolidate + single global slot ----------
    if (wid < 4) {
        // rows: 128 rows, 1 thread each (warps 0-3)
        const int r = wid * 32 + lane;
        float l8[8], o8[8];
        float4 a0 = rowc4[(r * 4 + 0) * 2], a1 = rowc4[(r * 4 + 0) * 2 + 1];
        l8[0]=a0.x; l8[1]=a0.y; l8[2]=a0.z; l8[3]=a0.w;
        l8[4]=a1.x; l8[5]=a1.y; l8[6]=a1.z; l8[7]=a1.w;
        #pragma unroll
        for (int s = 1; s < 4; s++) {
            float4 b0 = rowc4[(r * 4 + s) * 2], b1 = rowc4[(r * 4 + s) * 2 + 1];
            o8[0]=b0.x; o8[1]=b0.y; o8[2]=b0.z; o8[3]=b0.w;
            o8[4]=b1.x; o8[5]=b1.y; o8[6]=b1.z; o8[7]=b1.w;
            merge8(l8, o8);
        }
        float den = (rowden_s[r * 4] + rowden_s[r * 4 + 1]) +
                    (rowden_s[r * 4 + 2] + rowden_s[r * 4 + 3]);
        const int rg = i0 + r;
        const int slot = bj - bi;
        g_pden[(size_t)rg * SLOTS + slot] = den;
        float4* dst = (float4*)&g_cand[((size_t)rg * SLOTS + slot) * KNB];
        dst[0] = make_float4(l8[0], l8[1], l8[2], l8[3]);
        dst[1] = make_float4(l8[4], l8[5], l8[6], l8[7]);
    } else if (!diag) {
        // cols: 128 cols, 1 thread each (warps 4-7)
        const int c = (wid - 4) * 32 + lane;
        float l8[8], o8[8];
        float4 a0 = colc4[(c * 2) * 2], a1 = colc4[(c * 2) * 2 + 1];
        l8[0]=a0.x; l8[1]=a0.y; l8[2]=a0.z; l8[3]=a0.w;
        l8[4]=a1.x; l8[5]=a1.y; l8[6]=a1.z; l8[7]=a1.w;
        float4 b0 = colc4[(c * 2 + 1) * 2], b1 = colc4[(c * 2 + 1) * 2 + 1];
        o8[0]=b0.x; o8[1]=b0.y; o8[2]=b0.z; o8[3]=b0.w;
        o8[4]=b1.x; o8[5]=b1.y; o8[6]=b1.z; o8[7]=b1.w;
        merge8(l8, o8);
        float den = colden_s[c * 2] + colden_s[c * 2 + 1];
        const int cg = j0 + c;
        const int slot = COLBASE + bi;
        g_pden[(size_t)cg * SLOTS + slot] = den;
        float4* dst = (float4*)&g_cand[((size_t)cg * SLOTS + slot) * KNB];
        dst[0] = make_float4(l8[0], l8[1], l8[2], l8[3]);
        dst[1] = make_float4(l8[4], l8[5], l8[6], l8[7]);
    }
}

// ---------------------------------------------------------------------------
// merge kernel: one warp per row; exactly 64 slots -> 2 per lane, branch-free.
// ---------------------------------------------------------------------------
__global__ __launch_bounds__(256) void merge_kernel(int n) {
    const int row = (blockIdx.x * 256 + threadIdx.x) >> 5;
    const int lane = threadIdx.x & 31;
    const int br = row >> 7;
    const int nrow = NB - br;

    const int s0 = lane, s1 = lane + 32;
    const int slot0 = (s0 < nrow) ? s0 : (COLBASE + (s0 - nrow));
    const int slot1 = (s1 < nrow) ? s1 : (COLBASE + (s1 - nrow));

    const float4* p0 = (const float4*)&g_cand[((size_t)row * SLOTS + slot0) * KNB];
    const float4* p1 = (const float4*)&g_cand[((size_t)row * SLOTS + slot1) * KNB];
    float4 a0 = p0[0], a1 = p0[1], b0 = p1[0], b1 = p1[1];
    float pd = g_pden[(size_t)row * SLOTS + slot0] +
               g_pden[(size_t)row * SLOTS + slot1];

    float l8[8], o8[8];
    l8[0]=a0.x; l8[1]=a0.y; l8[2]=a0.z; l8[3]=a0.w;
    l8[4]=a1.x; l8[5]=a1.y; l8[6]=a1.z; l8[7]=a1.w;
    o8[0]=b0.x; o8[1]=b0.y; o8[2]=b0.z; o8[3]=b0.w;
    o8[4]=b1.x; o8[5]=b1.y; o8[6]=b1.z; o8[7]=b1.w;
    merge8(l8, o8);

    merge8_shfl(l8, 1);
    merge8_shfl(l8, 2);
    merge8_shfl(l8, 4);
    merge8_shfl(l8, 8);
    merge8_shfl(l8, 16);
    #pragma unroll
    for (int m = 1; m < 32; m <<= 1) pd += __shfl_xor_sync(0xffffffffu, pd, m);

    if (lane == 0) {
        float ds = 0.0f;
        #pragma unroll
        for (int q = 0; q < KNB; q++) ds += sqrtf(fmaxf(l8[q], 0.0f));
        g_loss[row] = ds * (1.0f / KNB) + logf(pd);
    }
}

// ---------------------------------------------------------------------------
__global__ void final_kernel(float* __restrict__ out, int n) {
    __shared__ float sv[256];
    const int tid = threadIdx.x;
    const float4* l4 = (const float4*)g_loss;
    float s = 0.0f;
    #pragma unroll
    for (int it = 0; it < NPTS / 1024; it++) {
        float4 v = l4[it * 256 + tid];
        s += (v.x + v.y) + (v.z + v.w);
    }
    sv[tid] = s;
    __syncthreads();
    for (int o = 128; o; o >>= 1) {
        if (tid < o) sv[tid] += sv[tid + o];
        __syncthreads();
    }
    if (tid == 0) out[0] = sv[0] / (float)n;
}

// ---------------------------------------------------------------------------
extern "C" void kernel_launch(void* const* d_in, const int* in_sizes, int n_in,
                              void* d_out, int out_size) {
    const float* x = (const float*)d_in[0];
    float* out = (float*)d_out;
    const int n = in_sizes[0] / DIM;   // 8192
    const int tri = NB * (NB + 1) / 2; // 2080

    cudaFuncSetAttribute(fused_gemm, cudaFuncAttributeMaxDynamicSharedMemorySize,
                         SMEM_TOTAL);

    pack_kernel<<<(n + 7) / 8, 256>>>(x, n);
    fused_gemm<<<tri, 256, SMEM_TOTAL>>>(n);
    merge_kernel<<<(n * 32) / 256, 256>>>(n);
    final_kernel<<<1, 256>>>(out, n);
}

// round 16
// speedup vs baseline: 1.0737x; 1.0737x over previous
#include <cuda_runtime.h>
#include <cuda_bf16.h>
#include <cuda_fp16.h>
#include <math.h>
#include <math_constants.h>
#include <cstdint>

#define NPTS 8192
#define DIM  128
#define KNB  8
#define NB   64            // 8192/128 blocks per side
#define SLOTS 384          // per row: 256 row-side + 128 col-side
#define COLBASE 256

// ------------------------- device scratch (no allocs) -----------------------
__device__ float g_sq[NPTS];
__device__ float g_loss[NPTS];
__device__ float g_pden[(size_t)NPTS * SLOTS];
__device__ __half g_cand[(size_t)NPTS * SLOTS * KNB];   // fp16 candidates
__device__ uint4 g_ph[(size_t)NPTS * 16];   // 128 bf16 (hi) per row
__device__ int g_ticket;

// ------------------------- helpers ------------------------------------------
__device__ __forceinline__ uint32_t smem_u32(const void* p) {
    uint32_t a;
    asm("{ .reg .u64 t; cvta.to.shared.u64 t, %1; cvt.u32.u64 %0, t; }"
        : "=r"(a) : "l"(p));
    return a;
}
#define SWZ(o) ((o) ^ (((o) >> 3) & 0x70))

#define CP_ASYNC16(dst, src) \
    asm volatile("cp.async.cg.shared.global [%0], [%1], 16;" \
                 :: "r"(dst), "l"(src) : "memory")
#define CP_COMMIT() asm volatile("cp.async.commit_group;" ::: "memory")
#define CP_WAIT(N)  asm volatile("cp.async.wait_group %0;" :: "n"(N) : "memory")

#define LDSM_X4(r0, r1, r2, r3, a) \
    asm volatile("ldmatrix.sync.aligned.m8n8.x4.shared.b16 {%0,%1,%2,%3}, [%4];" \
                 : "=r"(r0), "=r"(r1), "=r"(r2), "=r"(r3) : "r"(a))

#define MMA_BF16(c, a, b) \
    asm volatile("mma.sync.aligned.m16n8k16.row.col.f32.bf16.bf16.f32 " \
                 "{%0,%1,%2,%3}, {%4,%5,%6,%7}, {%8,%9}, {%0,%1,%2,%3};" \
                 : "+f"((c)[0]), "+f"((c)[1]), "+f"((c)[2]), "+f"((c)[3]) \
                 : "r"((a)[0]), "r"((a)[1]), "r"((a)[2]), "r"((a)[3]), \
                   "r"((b)[0]), "r"((b)[1]))

// SMEM: A tile 32KB at 0, B tile 32KB at 32KB (aliased to A on diagonal).
// 2 CTAs/SM -> 128KB of 227KB.
#define OFF_B    32768
#define SMEM_TOTAL 65536

// ---- MUFU transcendentals ---------------------------------------------------
__device__ __forceinline__ float rsqrt_ap(float x) {
    float y; asm("rsqrt.approx.f32 %0, %1;" : "=f"(y) : "f"(x)); return y;
}
__device__ __forceinline__ float ex2_ap(float x) {
    float y; asm("ex2.approx.f32 %0, %1;" : "=f"(y) : "f"(x)); return y;
}

// ---- fp16 candidate pack/unpack ---------------------------------------------
__device__ __forceinline__ uint4 pack8_h(const float* v) {
    __half2 h0 = __floats2half2_rn(v[0], v[1]);
    __half2 h1 = __floats2half2_rn(v[2], v[3]);
    __half2 h2 = __floats2half2_rn(v[4], v[5]);
    __half2 h3 = __floats2half2_rn(v[6], v[7]);
    uint4 r;
    r.x = *reinterpret_cast<uint32_t*>(&h0);
    r.y = *reinterpret_cast<uint32_t*>(&h1);
    r.z = *reinterpret_cast<uint32_t*>(&h2);
    r.w = *reinterpret_cast<uint32_t*>(&h3);
    return r;
}
__device__ __forceinline__ void unpack8_h(uint4 c, float* o) {
    float2 f0 = __half22float2(*reinterpret_cast<__half2*>(&c.x));
    float2 f1 = __half22float2(*reinterpret_cast<__half2*>(&c.y));
    float2 f2 = __half22float2(*reinterpret_cast<__half2*>(&c.z));
    float2 f3 = __half22float2(*reinterpret_cast<__half2*>(&c.w));
    o[0] = f0.x; o[1] = f0.y; o[2] = f1.x; o[3] = f1.y;
    o[4] = f2.x; o[5] = f2.y; o[6] = f3.x; o[7] = f3.y;
}

// ---- sorting networks -------------------------------------------------------
__device__ __forceinline__ void cas(float& a, float& b) {
    float lo = fminf(a, b), hi = fmaxf(a, b); a = lo; b = hi;
}
__device__ __forceinline__ void sort8(float* v) {
    cas(v[0],v[1]); cas(v[2],v[3]); cas(v[4],v[5]); cas(v[6],v[7]);
    cas(v[0],v[2]); cas(v[1],v[3]); cas(v[4],v[6]); cas(v[5],v[7]);
    cas(v[1],v[2]); cas(v[5],v[6]);
    cas(v[0],v[4]); cas(v[1],v[5]); cas(v[2],v[6]); cas(v[3],v[7]);
    cas(v[2],v[4]); cas(v[3],v[5]);
    cas(v[1],v[2]); cas(v[3],v[4]); cas(v[5],v[6]);
}
__device__ __forceinline__ void bitonic8(float* v) {
    cas(v[0],v[4]); cas(v[1],v[5]); cas(v[2],v[6]); cas(v[3],v[7]);
    cas(v[0],v[2]); cas(v[1],v[3]); cas(v[4],v[6]); cas(v[5],v[7]);
    cas(v[0],v[1]); cas(v[2],v[3]); cas(v[4],v[5]); cas(v[6],v[7]);
}
__device__ __forceinline__ void merge8(float* t, const float* o) {
    float m[8];
    #pragma unroll
    for (int q = 0; q < 8; q++) m[q] = fminf(t[q], o[7 - q]);
    bitonic8(m);
    #pragma unroll
    for (int q = 0; q < 8; q++) t[q] = m[q];
}
__device__ __forceinline__ void merge8_shfl(float* t, int mask) {
    float o[8];
    #pragma unroll
    for (int q = 0; q < 8; q++) o[q] = __shfl_xor_sync(0xffffffffu, t[7 - q], mask);
    #pragma unroll
    for (int q = 0; q < 8; q++) t[q] = fminf(t[q], o[q]);
    bitonic8(t);
}
// level-1 work-split merge: lane owns one of the two lists (ownb selects),
// exchanges the non-owned one with the xor-mask partner.
__device__ __forceinline__ void merge8_pair(float* r, const float* va,
                                            const float* vb, bool ownb,
                                            int mask) {
    #pragma unroll
    for (int q = 0; q < 8; q++) {
        float sendv = ownb ? va[7 - q] : vb[7 - q];
        float recvv = __shfl_xor_sync(0xffffffffu, sendv, mask);
        float minev = ownb ? vb[q] : va[q];
        r[q] = fminf(minev, recvv);
    }
    bitonic8(r);
}

// ---------------------------------------------------------------------------
// fused pack (hi only) + sqnorm: one warp per row. Also resets the ticket.
// ---------------------------------------------------------------------------
__global__ void pack_kernel(const float* __restrict__ x, int n) {
    if (blockIdx.x == 0 && threadIdx.x == 0) g_ticket = 0;
    int warp = (blockIdx.x * blockDim.x + threadIdx.x) >> 5;
    int lane = threadIdx.x & 31;
    if (warp >= n) return;
    float4 v = ((const float4*)(x + (size_t)warp * DIM))[lane];

    float s = v.x * v.x + v.y * v.y + v.z * v.z + v.w * v.w;
    #pragma unroll
    for (int o = 16; o; o >>= 1) s += __shfl_xor_sync(0xffffffffu, s, o);
    if (lane == 0) g_sq[warp] = s;

    __nv_bfloat162* ph2 = (__nv_bfloat162*)g_ph;   // 64 pairs per row
    size_t rb = (size_t)warp * 64;
    ph2[rb + lane * 2]     = __nv_bfloat162(__float2bfloat16(v.x), __float2bfloat16(v.y));
    ph2[rb + lane * 2 + 1] = __nv_bfloat162(__float2bfloat16(v.z), __float2bfloat16(v.w));
}

// ---------------------------------------------------------------------------
// Symmetric fused GEMM: 128x128 tiles over upper triangle, warps 2(m)x4(n)
// of 64x32. K=128 hi-only bf16; tiles SMEM-resident. Work-split merges,
// fp16 candidate stores. 2 CTAs/SM.
// ---------------------------------------------------------------------------
__global__ __launch_bounds__(256, 2) void fused_gemm(int n) {
    extern __shared__ __align__(16) char smem[];
    const uint32_t sb = smem_u32(smem);
    const int tid = threadIdx.x;
    const int wid = tid >> 5;
    const int lane = tid & 31;
    const int wm = wid & 1;          // 64-row half
    const int wn = wid >> 1;         // 32-col strip
    const int mr = wm * 64;
    const int nr = wn * 32;

    int rem = blockIdx.x, bi = 0;
    while (rem >= NB - bi) { rem -= NB - bi; bi++; }
    const int bj = bi + rem;
    const int i0 = bi * 128, j0 = bj * 128;
    const bool diag = (bi == bj);

    // prologue: A tile; B tile unless diagonal (B aliases A).
    #pragma unroll
    for (int r = 0; r < 8; r++) {
        int idx = tid + r * 256;                  // 0..2047
        int kc = idx >> 10, w = idx & 1023;
        int row = w >> 3, q = w & 7;
        const uint4* src = &g_ph[(size_t)(i0 + row) * 16 + kc * 8 + q];
        CP_ASYNC16(sb + kc * 16384 + SWZ(row * 128 + q * 16), src);
    }
    if (!diag) {
        #pragma unroll
        for (int r = 0; r < 8; r++) {
            int idx = tid + r * 256;
            int kc = idx >> 10, w = idx & 1023;
            int row = w >> 3, q = w & 7;
            const uint4* src = &g_ph[(size_t)(j0 + row) * 16 + kc * 8 + q];
            CP_ASYNC16(sb + OFF_B + kc * 16384 + SWZ(row * 128 + q * 16), src);
        }
    }
    CP_COMMIT();
    CP_WAIT(0);
    __syncthreads();

    const uint32_t bbase = diag ? sb : (sb + OFF_B);
    const int row_off = lane & 15;
    const int colh2 = (lane >> 4) * 16;
    const uint32_t aRow = (uint32_t)(mr + row_off) * 128;
    const uint32_t bRow = (uint32_t)(nr + row_off) * 128;

    float acc[4][4][4];
    #pragma unroll
    for (int i = 0; i < 4; i++)
        #pragma unroll
        for (int j = 0; j < 4; j++)
            #pragma unroll
            for (int q = 0; q < 4; q++) acc[i][j][q] = 0.0f;

    #pragma unroll
    for (int c = 0; c < 2; c++) {
        uint32_t sA = sb + c * 16384;
        uint32_t sB = bbase + c * 16384;
        #pragma unroll
        for (int ks = 0; ks < 4; ks++) {
            uint32_t colb = ks * 32 + colh2;
            uint32_t aF[4][4], bF[4][2];
            #pragma unroll
            for (int i = 0; i < 4; i++) {
                uint32_t ad = sA + SWZ(aRow + i * 2048 + colb);
                LDSM_X4(aF[i][0], aF[i][1], aF[i][2], aF[i][3], ad);
            }
            #pragma unroll
            for (int jj = 0; jj < 2; jj++) {
                uint32_t r0, r1, r2, r3;
                uint32_t bd = sB + SWZ(bRow + jj * 2048 + colb);
                LDSM_X4(r0, r1, r2, r3, bd);
                bF[2 * jj][0] = r0; bF[2 * jj][1] = r2;
                bF[2 * jj + 1][0] = r1; bF[2 * jj + 1][1] = r3;
            }
            #pragma unroll
            for (int i = 0; i < 4; i++)
                #pragma unroll
                for (int j = 0; j < 4; j++)
                    MMA_BF16(acc[i][j], aF[i], bF[j]);
        }
    }

    // ---------------- fused epilogue (work-split merges) ----------------
    const int g = lane >> 2, t = lane & 3;
    const int scol = j0 + nr + t * 2;
    const float NL2E = -1.4426950408889634f;

    float sqc[8], sqr[8], colden[8];
    #pragma unroll
    for (int j = 0; j < 4; j++) {
        #pragma unroll
        for (int e = 0; e < 2; e++) {
            sqc[j * 2 + e] = g_sq[scol + j * 8 + e];
            colden[j * 2 + e] = 0.0f;
        }
    }
    #pragma unroll
    for (int i = 0; i < 4; i++)
        #pragma unroll
        for (int h = 0; h < 2; h++)
            sqr[i * 2 + h] = g_sq[i0 + mr + i * 16 + h * 8 + g];

    const int rslot = (bj - bi) * 4 + wn;
    const bool own_h1 = (lane & 1);          // t parity: odd t owns h=1
    #pragma unroll
    for (int i = 0; i < 4; i++) {
        const int rga = i0 + mr + i * 16 + g;       // h = 0
        const int rgb = rga + 8;                    // h = 1
        const float sqia = sqr[i * 2], sqib = sqr[i * 2 + 1];
        float v8a[8], v8b[8];
        float den_a = 0.0f, den_b = 0.0f;
        #pragma unroll
        for (int j = 0; j < 4; j++) {
            #pragma unroll
            for (int e = 0; e < 2; e++) {
                const int je = j * 2 + e;
                const int cg = scol + j * 8 + e;
                float d2a = fmaxf(fmaf(-2.0f, acc[i][j][e], sqia + sqc[je]), 0.0f);
                bool sa = diag && (cg == rga);
                float exa = ex2_ap(d2a * rsqrt_ap(d2a) * NL2E);
                exa = sa ? 0.0f : exa;
                den_a += exa; colden[je] += exa;
                v8a[je] = sa ? CUDART_INF_F : d2a;

                float d2b = fmaxf(fmaf(-2.0f, acc[i][j][2 + e], sqib + sqc[je]), 0.0f);
                bool sbx = diag && (cg == rgb);
                float exb = ex2_ap(d2b * rsqrt_ap(d2b) * NL2E);
                exb = sbx ? 0.0f : exb;
                den_b += exb; colden[je] += exb;
                v8b[je] = sbx ? CUDART_INF_F : d2b;
            }
        }
        den_a += __shfl_xor_sync(0xffffffffu, den_a, 1);
        den_a += __shfl_xor_sync(0xffffffffu, den_a, 2);
        den_b += __shfl_xor_sync(0xffffffffu, den_b, 1);
        den_b += __shfl_xor_sync(0xffffffffu, den_b, 2);
        sort8(v8a); sort8(v8b);
        float r8[8];
        merge8_pair(r8, v8a, v8b, own_h1, 1);   // t0<->t1, t2<->t3
        merge8_shfl(r8, 2);                     // complete over 4 t-lanes
        if (t < 2) {                            // t==0 owns h=0, t==1 h=1
            const int rg_own = own_h1 ? rgb : rga;
            g_pden[(size_t)rg_own * SLOTS + rslot] = own_h1 ? den_b : den_a;
            *(uint4*)&g_cand[((size_t)rg_own * SLOTS + rslot) * KNB] = pack8_h(r8);
        }
    }

    if (!diag) {
        const int cslot = COLBASE + bi * 2 + wm;
        const bool own_e1 = (lane >> 2) & 1;    // g parity: odd g owns e=1
        #pragma unroll
        for (int j = 0; j < 4; j++) {
            float c8a[8], c8b[8];
            #pragma unroll
            for (int i = 0; i < 4; i++) {
                #pragma unroll
                for (int h = 0; h < 2; h++) {
                    float sq_ih = sqr[i * 2 + h];
                    c8a[i * 2 + h] = fmaxf(fmaf(-2.0f, acc[i][j][h * 2],     sq_ih + sqc[j * 2]),     0.0f);
                    c8b[i * 2 + h] = fmaxf(fmaf(-2.0f, acc[i][j][h * 2 + 1], sq_ih + sqc[j * 2 + 1]), 0.0f);
                }
            }
            sort8(c8a); sort8(c8b);
            float r8[8];
            merge8_pair(r8, c8a, c8b, own_e1, 4);   // g pairs
            merge8_shfl(r8, 8);
            merge8_shfl(r8, 16);                    // complete over 8 g-lanes
            float cda = colden[j * 2], cdb = colden[j * 2 + 1];
            cda += __shfl_xor_sync(0xffffffffu, cda, 4);
            cda += __shfl_xor_sync(0xffffffffu, cda, 8);
            cda += __shfl_xor_sync(0xffffffffu, cda, 16);
            cdb += __shfl_xor_sync(0xffffffffu, cdb, 4);
            cdb += __shfl_xor_sync(0xffffffffu, cdb, 8);
            cdb += __shfl_xor_sync(0xffffffffu, cdb, 16);
            if (g < 2) {                            // g==0 owns e=0, g==1 e=1
                const int cg = scol + j * 8 + (own_e1 ? 1 : 0);
                g_pden[(size_t)cg * SLOTS + cslot] = own_e1 ? cdb : cda;
                *(uint4*)&g_cand[((size_t)cg * SLOTS + cslot) * KNB] = pack8_h(r8);
            }
        }
    }
}

// ---------------------------------------------------------------------------
// merge kernel: one warp per row; software-pipelined slot loads (MLP=2);
// fp16 candidates; last block folds the final reduction (fixed order).
// ---------------------------------------------------------------------------
__global__ __launch_bounds__(256) void merge_kernel(float* __restrict__ out, int n) {
    const int row = (blockIdx.x * 256 + threadIdx.x) >> 5;
    const int lane = threadIdx.x & 31;
    const int bi = row >> 7;
    const int nrow = (NB - bi) * 4;
    const int ntot = nrow + 2 * bi;

    float l8[8];
    #pragma unroll
    for (int q = 0; q < 8; q++) l8[q] = CUDART_INF_F;
    float den = 0.0f;

    int s = lane;
    uint4 c; float pd = 0.0f;
    if (s < ntot) {
        int slot = (s < nrow) ? s : (COLBASE + (s - nrow));
        c = *(const uint4*)&g_cand[((size_t)row * SLOTS + slot) * KNB];
        pd = g_pden[(size_t)row * SLOTS + slot];
    }
    while (s < ntot) {
        int s2 = s + 32;
        uint4 c2; float pd2 = 0.0f;
        if (s2 < ntot) {
            int slot2 = (s2 < nrow) ? s2 : (COLBASE + (s2 - nrow));
            c2 = *(const uint4*)&g_cand[((size_t)row * SLOTS + slot2) * KNB];
            pd2 = g_pden[(size_t)row * SLOTS + slot2];
        }
        float o[8];
        unpack8_h(c, o);
        merge8(l8, o);
        den += pd;
        c = c2; pd = pd2; s = s2;
    }
    merge8_shfl(l8, 1);
    merge8_shfl(l8, 2);
    merge8_shfl(l8, 4);
    merge8_shfl(l8, 8);
    merge8_shfl(l8, 16);
    #pragma unroll
    for (int m = 1; m < 32; m <<= 1) den += __shfl_xor_sync(0xffffffffu, den, m);

    if (lane == 0) {
        float ds = 0.0f;
        #pragma unroll
        for (int q = 0; q < KNB; q++) ds += sqrtf(fmaxf(l8[q], 0.0f));
        g_loss[row] = ds * (1.0f / KNB) + logf(den);
    }

    // -------- deterministic final reduction in the last-arriving block -----
    __shared__ int s_last;
    __shared__ float sv[256];
    __syncthreads();
    if (threadIdx.x == 0) {
        __threadfence();
        int old = atomicAdd(&g_ticket, 1);
        s_last = (old == (int)gridDim.x - 1) ? 1 : 0;
    }
    __syncthreads();
    if (s_last) {
        const int tid = threadIdx.x;
        const float4* l4 = (const float4*)g_loss;
        float sum = 0.0f;
        #pragma unroll
        for (int it = 0; it < NPTS / 1024; it++) {
            float4 v = l4[it * 256 + tid];
            sum += (v.x + v.y) + (v.z + v.w);
        }
        sv[tid] = sum;
        __syncthreads();
        for (int o = 128; o; o >>= 1) {
            if (tid < o) sv[tid] += sv[tid + o];
            __syncthreads();
        }
        if (tid == 0) out[0] = sv[0] / (float)n;
    }
}

// ---------------------------------------------------------------------------
extern "C" void kernel_launch(void* const* d_in, const int* in_sizes, int n_in,
                              void* d_out, int out_size) {
    const float* x = (const float*)d_in[0];
    float* out = (float*)d_out;
    const int n = in_sizes[0] / DIM;   // 8192
    const int tri = NB * (NB + 1) / 2; // 2080

    cudaFuncSetAttribute(fused_gemm, cudaFuncAttributeMaxDynamicSharedMemorySize,
                         SMEM_TOTAL);

    pack_kernel<<<(n + 7) / 8, 256>>>(x, n);
    fused_gemm<<<tri, 256, SMEM_TOTAL>>>(n);
    merge_kernel<<<(n * 32) / 256, 256>>>(out, n);
}

// round 17
// speedup vs baseline: 1.0822x; 1.0079x over previous
#include <cuda_runtime.h>
#include <cuda_bf16.h>
#include <cuda_fp16.h>
#include <math.h>
#include <math_constants.h>
#include <cstdint>

#define NPTS 8192
#define DIM  128
#define KNB  8
#define NB   64            // 8192/128 blocks per side
#define SLOTS 384          // per row: 256 row-side + 128 col-side
#define COLBASE 256

// ------------------------- device scratch (no allocs) -----------------------
__device__ float g_sq[NPTS];
__device__ float g_loss[NPTS];
__device__ float g_pden[(size_t)NPTS * SLOTS];
__device__ __half g_cand[(size_t)NPTS * SLOTS * KNB];   // fp16 candidates
__device__ uint4 g_ph[(size_t)NPTS * 16];   // 128 bf16 (hi) per row
__device__ int g_ticket;

// ------------------------- helpers ------------------------------------------
__device__ __forceinline__ uint32_t smem_u32(const void* p) {
    uint32_t a;
    asm("{ .reg .u64 t; cvta.to.shared.u64 t, %1; cvt.u32.u64 %0, t; }"
        : "=r"(a) : "l"(p));
    return a;
}
#define SWZ(o) ((o) ^ (((o) >> 3) & 0x70))

#define CP_ASYNC16(dst, src) \
    asm volatile("cp.async.cg.shared.global [%0], [%1], 16;" \
                 :: "r"(dst), "l"(src) : "memory")
#define CP_COMMIT() asm volatile("cp.async.commit_group;" ::: "memory")
#define CP_WAIT(N)  asm volatile("cp.async.wait_group %0;" :: "n"(N) : "memory")

#define LDSM_X4(r0, r1, r2, r3, a) \
    asm volatile("ldmatrix.sync.aligned.m8n8.x4.shared.b16 {%0,%1,%2,%3}, [%4];" \
                 : "=r"(r0), "=r"(r1), "=r"(r2), "=r"(r3) : "r"(a))

#define MMA_BF16(c, a, b) \
    asm volatile("mma.sync.aligned.m16n8k16.row.col.f32.bf16.bf16.f32 " \
                 "{%0,%1,%2,%3}, {%4,%5,%6,%7}, {%8,%9}, {%0,%1,%2,%3};" \
                 : "+f"((c)[0]), "+f"((c)[1]), "+f"((c)[2]), "+f"((c)[3]) \
                 : "r"((a)[0]), "r"((a)[1]), "r"((a)[2]), "r"((a)[3]), \
                   "r"((b)[0]), "r"((b)[1]))

// SMEM: A tile 32KB at 0, B tile 32KB at 32KB (aliased to A on diagonal).
// 2 CTAs/SM -> 128KB of 227KB.
#define OFF_B    32768
#define SMEM_TOTAL 65536

// ---- MUFU transcendentals ---------------------------------------------------
__device__ __forceinline__ float rsqrt_ap(float x) {
    float y; asm("rsqrt.approx.f32 %0, %1;" : "=f"(y) : "f"(x)); return y;
}
__device__ __forceinline__ float ex2_ap(float x) {
    float y; asm("ex2.approx.f32 %0, %1;" : "=f"(y) : "f"(x)); return y;
}

// ---- fp16 candidate pack/unpack ---------------------------------------------
__device__ __forceinline__ uint4 pack8_h(const float* v) {
    __half2 h0 = __floats2half2_rn(v[0], v[1]);
    __half2 h1 = __floats2half2_rn(v[2], v[3]);
    __half2 h2 = __floats2half2_rn(v[4], v[5]);
    __half2 h3 = __floats2half2_rn(v[6], v[7]);
    uint4 r;
    r.x = *reinterpret_cast<uint32_t*>(&h0);
    r.y = *reinterpret_cast<uint32_t*>(&h1);
    r.z = *reinterpret_cast<uint32_t*>(&h2);
    r.w = *reinterpret_cast<uint32_t*>(&h3);
    return r;
}
__device__ __forceinline__ void unpack8_h(uint4 c, float* o) {
    float2 f0 = __half22float2(*reinterpret_cast<__half2*>(&c.x));
    float2 f1 = __half22float2(*reinterpret_cast<__half2*>(&c.y));
    float2 f2 = __half22float2(*reinterpret_cast<__half2*>(&c.z));
    float2 f3 = __half22float2(*reinterpret_cast<__half2*>(&c.w));
    o[0] = f0.x; o[1] = f0.y; o[2] = f1.x; o[3] = f1.y;
    o[4] = f2.x; o[5] = f2.y; o[6] = f3.x; o[7] = f3.y;
}

// ---- sorting networks -------------------------------------------------------
__device__ __forceinline__ void cas(float& a, float& b) {
    float lo = fminf(a, b), hi = fmaxf(a, b); a = lo; b = hi;
}
__device__ __forceinline__ void sort8(float* v) {
    cas(v[0],v[1]); cas(v[2],v[3]); cas(v[4],v[5]); cas(v[6],v[7]);
    cas(v[0],v[2]); cas(v[1],v[3]); cas(v[4],v[6]); cas(v[5],v[7]);
    cas(v[1],v[2]); cas(v[5],v[6]);
    cas(v[0],v[4]); cas(v[1],v[5]); cas(v[2],v[6]); cas(v[3],v[7]);
    cas(v[2],v[4]); cas(v[3],v[5]);
    cas(v[1],v[2]); cas(v[3],v[4]); cas(v[5],v[6]);
}
__device__ __forceinline__ void bitonic8(float* v) {
    cas(v[0],v[4]); cas(v[1],v[5]); cas(v[2],v[6]); cas(v[3],v[7]);
    cas(v[0],v[2]); cas(v[1],v[3]); cas(v[4],v[6]); cas(v[5],v[7]);
    cas(v[0],v[1]); cas(v[2],v[3]); cas(v[4],v[5]); cas(v[6],v[7]);
}
__device__ __forceinline__ void merge8(float* t, const float* o) {
    float m[8];
    #pragma unroll
    for (int q = 0; q < 8; q++) m[q] = fminf(t[q], o[7 - q]);
    bitonic8(m);
    #pragma unroll
    for (int q = 0; q < 8; q++) t[q] = m[q];
}
__device__ __forceinline__ void merge8_shfl(float* t, int mask) {
    float o[8];
    #pragma unroll
    for (int q = 0; q < 8; q++) o[q] = __shfl_xor_sync(0xffffffffu, t[7 - q], mask);
    #pragma unroll
    for (int q = 0; q < 8; q++) t[q] = fminf(t[q], o[q]);
    bitonic8(t);
}
// level-1 work-split merge: lane owns one of the two lists (ownb selects),
// exchanges the non-owned one with the xor-mask partner.
__device__ __forceinline__ void merge8_pair(float* r, const float* va,
                                            const float* vb, bool ownb,
                                            int mask) {
    #pragma unroll
    for (int q = 0; q < 8; q++) {
        float sendv = ownb ? va[7 - q] : vb[7 - q];
        float recvv = __shfl_xor_sync(0xffffffffu, sendv, mask);
        float minev = ownb ? vb[q] : va[q];
        r[q] = fminf(minev, recvv);
    }
    bitonic8(r);
}

// ---------------------------------------------------------------------------
// fused pack (hi only) + sqnorm: one warp per row. Also resets the ticket.
// ---------------------------------------------------------------------------
__global__ void pack_kernel(const float* __restrict__ x, int n) {
    if (blockIdx.x == 0 && threadIdx.x == 0) g_ticket = 0;
    int warp = (blockIdx.x * blockDim.x + threadIdx.x) >> 5;
    int lane = threadIdx.x & 31;
    if (warp >= n) return;
    float4 v = ((const float4*)(x + (size_t)warp * DIM))[lane];

    float s = v.x * v.x + v.y * v.y + v.z * v.z + v.w * v.w;
    #pragma unroll
    for (int o = 16; o; o >>= 1) s += __shfl_xor_sync(0xffffffffu, s, o);
    if (lane == 0) g_sq[warp] = s;

    __nv_bfloat162* ph2 = (__nv_bfloat162*)g_ph;   // 64 pairs per row
    size_t rb = (size_t)warp * 64;
    ph2[rb + lane * 2]     = __nv_bfloat162(__float2bfloat16(v.x), __float2bfloat16(v.y));
    ph2[rb + lane * 2 + 1] = __nv_bfloat162(__float2bfloat16(v.z), __float2bfloat16(v.w));
}

// ---------------------------------------------------------------------------
// Symmetric fused GEMM: 128x128 tiles over upper triangle, warps 2(m)x4(n)
// of 64x32. K=128 hi-only bf16; chunked prologue overlaps load with MMA.
// Work-split merges, fp16 candidate stores. 2 CTAs/SM.
// ---------------------------------------------------------------------------
__global__ __launch_bounds__(256, 2) void fused_gemm(int n) {
    extern __shared__ __align__(16) char smem[];
    const uint32_t sb = smem_u32(smem);
    const int tid = threadIdx.x;
    const int wid = tid >> 5;
    const int lane = tid & 31;
    const int wm = wid & 1;          // 64-row half
    const int wn = wid >> 1;         // 32-col strip
    const int mr = wm * 64;
    const int nr = wn * 32;

    // closed-form triangular decode + bounded fix-up
    const int bid = blockIdx.x;
    int bi = (int)((129.0f - sqrtf(fmaxf(16641.0f - 8.0f * (float)bid, 0.0f))) * 0.5f);
    if (bi > NB - 1) bi = NB - 1;
    if (bi < 0) bi = 0;
    int off = bi * NB - (bi * (bi - 1)) / 2;
    while (off > bid) { bi--; off -= NB - bi; }
    while (bid >= off + (NB - bi)) { off += NB - bi; bi++; }
    const int bj = bi + (bid - off);
    const int i0 = bi * 128, j0 = bj * 128;
    const bool diag = (bi == bj);

    // chunked prologue: group0 = A0 (+B0), group1 = A1 (+B1)
    #pragma unroll
    for (int kc = 0; kc < 2; kc++) {
        #pragma unroll
        for (int r = 0; r < 4; r++) {
            int idx = tid + r * 256;              // 0..1023
            int row = idx >> 3, q = idx & 7;
            const uint4* src = &g_ph[(size_t)(i0 + row) * 16 + kc * 8 + q];
            CP_ASYNC16(sb + kc * 16384 + SWZ(row * 128 + q * 16), src);
        }
        if (!diag) {
            #pragma unroll
            for (int r = 0; r < 4; r++) {
                int idx = tid + r * 256;
                int row = idx >> 3, q = idx & 7;
                const uint4* src = &g_ph[(size_t)(j0 + row) * 16 + kc * 8 + q];
                CP_ASYNC16(sb + OFF_B + kc * 16384 + SWZ(row * 128 + q * 16), src);
            }
        }
        CP_COMMIT();
    }

    const uint32_t bbase = diag ? sb : (sb + OFF_B);
    const int row_off = lane & 15;
    const int colh2 = (lane >> 4) * 16;
    const uint32_t aRow = (uint32_t)(mr + row_off) * 128;
    const uint32_t bRow = (uint32_t)(nr + row_off) * 128;

    float acc[4][4][4];
    #pragma unroll
    for (int i = 0; i < 4; i++)
        #pragma unroll
        for (int j = 0; j < 4; j++)
            #pragma unroll
            for (int q = 0; q < 4; q++) acc[i][j][q] = 0.0f;

    #pragma unroll
    for (int c = 0; c < 2; c++) {
        if (c == 0) CP_WAIT(1); else CP_WAIT(0);
        __syncthreads();
        uint32_t sA = sb + c * 16384;
        uint32_t sB = bbase + c * 16384;
        #pragma unroll
        for (int ks = 0; ks < 4; ks++) {
            uint32_t colb = ks * 32 + colh2;
            uint32_t aF[4][4], bF[4][2];
            #pragma unroll
            for (int i = 0; i < 4; i++) {
                uint32_t ad = sA + SWZ(aRow + i * 2048 + colb);
                LDSM_X4(aF[i][0], aF[i][1], aF[i][2], aF[i][3], ad);
            }
            #pragma unroll
            for (int jj = 0; jj < 2; jj++) {
                uint32_t r0, r1, r2, r3;
                uint32_t bd = sB + SWZ(bRow + jj * 2048 + colb);
                LDSM_X4(r0, r1, r2, r3, bd);
                bF[2 * jj][0] = r0; bF[2 * jj][1] = r2;
                bF[2 * jj + 1][0] = r1; bF[2 * jj + 1][1] = r3;
            }
            #pragma unroll
            for (int i = 0; i < 4; i++)
                #pragma unroll
                for (int j = 0; j < 4; j++)
                    MMA_BF16(acc[i][j], aF[i], bF[j]);
        }
    }

    // ---------------- fused epilogue (work-split merges) ----------------
    const int g = lane >> 2, t = lane & 3;
    const int scol = j0 + nr + t * 2;
    const float NL2E = -1.4426950408889634f;

    float sqc[8], sqr[8], colden[8];
    #pragma unroll
    for (int j = 0; j < 4; j++) {
        #pragma unroll
        for (int e = 0; e < 2; e++) {
            sqc[j * 2 + e] = g_sq[scol + j * 8 + e];
            colden[j * 2 + e] = 0.0f;
        }
    }
    #pragma unroll
    for (int i = 0; i < 4; i++)
        #pragma unroll
        for (int h = 0; h < 2; h++)
            sqr[i * 2 + h] = g_sq[i0 + mr + i * 16 + h * 8 + g];

    const int rslot = (bj - bi) * 4 + wn;
    const bool own_h1 = (lane & 1);          // t parity: odd t owns h=1
    #pragma unroll
    for (int i = 0; i < 4; i++) {
        const int rga = i0 + mr + i * 16 + g;       // h = 0
        const int rgb = rga + 8;                    // h = 1
        const float sqia = sqr[i * 2], sqib = sqr[i * 2 + 1];
        float v8a[8], v8b[8];
        float den_a = 0.0f, den_b = 0.0f;
        #pragma unroll
        for (int j = 0; j < 4; j++) {
            #pragma unroll
            for (int e = 0; e < 2; e++) {
                const int je = j * 2 + e;
                const int cg = scol + j * 8 + e;
                float d2a = fmaxf(fmaf(-2.0f, acc[i][j][e], sqia + sqc[je]), 0.0f);
                bool sa = diag && (cg == rga);
                float exa = ex2_ap(d2a * rsqrt_ap(d2a) * NL2E);
                exa = sa ? 0.0f : exa;
                den_a += exa; colden[je] += exa;
                v8a[je] = sa ? CUDART_INF_F : d2a;

                float d2b = fmaxf(fmaf(-2.0f, acc[i][j][2 + e], sqib + sqc[je]), 0.0f);
                bool sbx = diag && (cg == rgb);
                float exb = ex2_ap(d2b * rsqrt_ap(d2b) * NL2E);
                exb = sbx ? 0.0f : exb;
                den_b += exb; colden[je] += exb;
                v8b[je] = sbx ? CUDART_INF_F : d2b;
            }
        }
        den_a += __shfl_xor_sync(0xffffffffu, den_a, 1);
        den_a += __shfl_xor_sync(0xffffffffu, den_a, 2);
        den_b += __shfl_xor_sync(0xffffffffu, den_b, 1);
        den_b += __shfl_xor_sync(0xffffffffu, den_b, 2);
        sort8(v8a); sort8(v8b);
        float r8[8];
        merge8_pair(r8, v8a, v8b, own_h1, 1);   // t0<->t1, t2<->t3
        merge8_shfl(r8, 2);                     // complete over 4 t-lanes
        if (t < 2) {                            // t==0 owns h=0, t==1 h=1
            const int rg_own = own_h1 ? rgb : rga;
            g_pden[(size_t)rg_own * SLOTS + rslot] = own_h1 ? den_b : den_a;
            *(uint4*)&g_cand[((size_t)rg_own * SLOTS + rslot) * KNB] = pack8_h(r8);
        }
    }

    if (!diag) {
        const int cslot = COLBASE + bi * 2 + wm;
        const bool own_e1 = (lane >> 2) & 1;    // g parity: odd g owns e=1
        #pragma unroll
        for (int j = 0; j < 4; j++) {
            float c8a[8], c8b[8];
            #pragma unroll
            for (int i = 0; i < 4; i++) {
                #pragma unroll
                for (int h = 0; h < 2; h++) {
                    float sq_ih = sqr[i * 2 + h];
                    c8a[i * 2 + h] = fmaxf(fmaf(-2.0f, acc[i][j][h * 2],     sq_ih + sqc[j * 2]),     0.0f);
                    c8b[i * 2 + h] = fmaxf(fmaf(-2.0f, acc[i][j][h * 2 + 1], sq_ih + sqc[j * 2 + 1]), 0.0f);
                }
            }
            sort8(c8a); sort8(c8b);
            float r8[8];
            merge8_pair(r8, c8a, c8b, own_e1, 4);   // g pairs
            merge8_shfl(r8, 8);
            merge8_shfl(r8, 16);                    // complete over 8 g-lanes
            float cda = colden[j * 2], cdb = colden[j * 2 + 1];
            cda += __shfl_xor_sync(0xffffffffu, cda, 4);
            cda += __shfl_xor_sync(0xffffffffu, cda, 8);
            cda += __shfl_xor_sync(0xffffffffu, cda, 16);
            cdb += __shfl_xor_sync(0xffffffffu, cdb, 4);
            cdb += __shfl_xor_sync(0xffffffffu, cdb, 8);
            cdb += __shfl_xor_sync(0xffffffffu, cdb, 16);
            if (g < 2) {                            // g==0 owns e=0, g==1 e=1
                const int cg = scol + j * 8 + (own_e1 ? 1 : 0);
                g_pden[(size_t)cg * SLOTS + cslot] = own_e1 ? cdb : cda;
                *(uint4*)&g_cand[((size_t)cg * SLOTS + cslot) * KNB] = pack8_h(r8);
            }
        }
    }
}

// ---------------------------------------------------------------------------
// merge kernel: one warp per row; software-pipelined slot loads (MLP=2);
// fp16 candidates; last block folds the final reduction (fixed order).
// ---------------------------------------------------------------------------
__global__ __launch_bounds__(256) void merge_kernel(float* __restrict__ out, int n) {
    const int row = (blockIdx.x * 256 + threadIdx.x) >> 5;
    const int lane = threadIdx.x & 31;
    const int bi = row >> 7;
    const int nrow = (NB - bi) * 4;
    const int ntot = nrow + 2 * bi;

    float l8[8];
    #pragma unroll
    for (int q = 0; q < 8; q++) l8[q] = CUDART_INF_F;
    float den = 0.0f;

    int s = lane;
    uint4 c; float pd = 0.0f;
    if (s < ntot) {
        int slot = (s < nrow) ? s : (COLBASE + (s - nrow));
        c = *(const uint4*)&g_cand[((size_t)row * SLOTS + slot) * KNB];
        pd = g_pden[(size_t)row * SLOTS + slot];
    }
    while (s < ntot) {
        int s2 = s + 32;
        uint4 c2; float pd2 = 0.0f;
        if (s2 < ntot) {
            int slot2 = (s2 < nrow) ? s2 : (COLBASE + (s2 - nrow));
            c2 = *(const uint4*)&g_cand[((size_t)row * SLOTS + slot2) * KNB];
            pd2 = g_pden[(size_t)row * SLOTS + slot2];
        }
        float o[8];
        unpack8_h(c, o);
        merge8(l8, o);
        den += pd;
        c = c2; pd = pd2; s = s2;
    }
    merge8_shfl(l8, 1);
    merge8_shfl(l8, 2);
    merge8_shfl(l8, 4);
    merge8_shfl(l8, 8);
    merge8_shfl(l8, 16);
    #pragma unroll
    for (int m = 1; m < 32; m <<= 1) den += __shfl_xor_sync(0xffffffffu, den, m);

    if (lane == 0) {
        float ds = 0.0f;
        #pragma unroll
        for (int q = 0; q < KNB; q++) ds += sqrtf(fmaxf(l8[q], 0.0f));
        g_loss[row] = ds * (1.0f / KNB) + logf(den);
    }

    // -------- deterministic final reduction in the last-arriving block -----
    __shared__ int s_last;
    __shared__ float sv[256];
    __syncthreads();
    if (threadIdx.x == 0) {
        __threadfence();
        int old = atomicAdd(&g_ticket, 1);
        s_last = (old == (int)gridDim.x - 1) ? 1 : 0;
    }
    __syncthreads();
    if (s_last) {
        const int tid = threadIdx.x;
        const float4* l4 = (const float4*)g_loss;
        float sum = 0.0f;
        #pragma unroll
        for (int it = 0; it < NPTS / 1024; it++) {
            float4 v = l4[it * 256 + tid];
            sum += (v.x + v.y) + (v.z + v.w);
        }
        sv[tid] = sum;
        __syncthreads();
        for (int o = 128; o; o >>= 1) {
            if (tid < o) sv[tid] += sv[tid + o];
            __syncthreads();
        }
        if (tid == 0) out[0] = sv[0] / (float)n;
    }
}

// ---------------------------------------------------------------------------
extern "C" void kernel_launch(void* const* d_in, const int* in_sizes, int n_in,
                              void* d_out, int out_size) {
    const float* x = (const float*)d_in[0];
    float* out = (float*)d_out;
    const int n = in_sizes[0] / DIM;   // 8192
    const int tri = NB * (NB + 1) / 2; // 2080

    cudaFuncSetAttribute(fused_gemm, cudaFuncAttributeMaxDynamicSharedMemorySize,
                         SMEM_TOTAL);

    pack_kernel<<<(n + 7) / 8, 256>>>(x, n);
    fused_gemm<<<tri, 256, SMEM_TOTAL>>>(n);
    merge_kernel<<<(n * 32) / 256, 256>>>(out, n);
}